// round 5
// baseline (speedup 1.0000x reference)
#include <cuda_runtime.h>
#include <cuda_fp16.h>

// SpikeCNN fused: one block = one image, all 8 timesteps.
// R5: conv2 LDS-byte reduction: oc-paired warps (v window shared by 2 ocs),
//     p1 stored as fp16 (exact for spike-pool values), broadcast weight rows.

#define TH 1.0f
#define TSTEPS 8
#define NT 224
#define XPITCH 33          // xpadT: col*33 + row (col-major)
#define C1CP 30            // c1s: c*840 + col*30 + row (col-major)
#define P1P 12             // p1h: [ic][rh(36)][k(12)] halves (k 0..10 used)

__global__ __launch_bounds__(NT, 3)
void snn_kernel(const float* __restrict__ x,
                const float* __restrict__ w1, const float* __restrict__ b1,
                const float* __restrict__ w2, const float* __restrict__ b2,
                const float* __restrict__ wf, const float* __restrict__ bf,
                float* __restrict__ out, int nb)
{
    __shared__ __align__(16) float  xpadT[32 * XPITCH];   // 1056 f32
    __shared__ __align__(16) float  c1s[3 * 28 * C1CP];   // 2520 f32 (col-major)
    __shared__ __align__(16) __half p1h[3 * 36 * P1P];    // 1296 halves
    __shared__ __align__(16) float  w2d[6 * 3 * 5 * 8];   // [oc][ic][di][8] padded rows
    __shared__ float s2L[6 * 196];          // oc*196 + j*28 + (row*2+h)
    __shared__ float p2s[294];
    __shared__ float fcsum[10], mem3s[10], acc3s[10];

    const int tid  = threadIdx.x;
    const int warp = tid >> 5;              // 0..6
    const int lane = tid & 31;
    const int b    = blockIdx.x;

    // ---- init ----
    for (int i = tid; i < 32 * XPITCH; i += NT)  xpadT[i] = 0.f;
    for (int i = tid; i < 3 * 36 * P1P; i += NT) p1h[i]   = __float2half(0.f);
    for (int i = tid; i < 720; i += NT)          w2d[i]   = 0.f;
    if (tid < 10) { mem3s[tid] = 0.f; acc3s[tid] = 0.f; }
    __syncthreads();
    for (int i = tid; i < 450; i += NT) {
        int g = i / 5, dj = i - 5 * g;      // g = oc*15 + ic*5 + di
        w2d[g * 8 + dj] = w2[i];
    }
    const float* xb = x + (size_t)b * 784;
    for (int i = tid; i < 784; i += NT) {
        int r = i / 28, c = i % 28;
        xpadT[(c + 2) * XPITCH + (r + 2)] = xb[i];
    }
    __syncthreads();

    // ---- conv1 (once): warps 0..5 -> (c = warp%3, colhalf = warp/3), lane = row ----
    if (warp < 6 && lane < 28) {
        int c = warp % 3, colbase = (warp / 3) * 14, row = lane;
        float wr[25];
        #pragma unroll
        for (int k = 0; k < 25; k++) wr[k] = __ldg(&w1[c * 25 + k]);
        float bias = __ldg(&b1[c]);
        float acc[14];
        #pragma unroll
        for (int j = 0; j < 14; j++) acc[j] = bias;
        #pragma unroll
        for (int di = 0; di < 5; di++) {
            float v[18];
            #pragma unroll
            for (int k = 0; k < 18; k++)
                v[k] = xpadT[(colbase + k) * XPITCH + row + di];
            #pragma unroll
            for (int j = 0; j < 14; j++)
                #pragma unroll
                for (int dj = 0; dj < 5; dj++)
                    acc[j] += v[j + dj] * wr[di * 5 + dj];
        }
        #pragma unroll
        for (int j = 0; j < 14; j++)
            c1s[c * 840 + (colbase + j) * C1CP + row] = acc[j];
    }
    __syncthreads();

    // ---- persistent register state ----
    float mr[12];                           // mem1: 3 tasks x 4 cells (all 7 warps)
    #pragma unroll
    for (int i = 0; i < 12; i++) mr[i] = 0.f;
    // mem2: warps 0..2 own oc pair {2w, 2w+1}, 7 cols each
    float m2a[7], m2b[7];
    #pragma unroll
    for (int j = 0; j < 7; j++) { m2a[j] = 0.f; m2b[j] = 0.f; }
    const bool bact = (warp < 3 && lane < 28);
    const float b2a = bact ? __ldg(&b2[2 * warp])     : 0.f;
    const float b2b = bact ? __ldg(&b2[2 * warp + 1]) : 0.f;

    const int  pi   = lane % 14;            // phase-A pooled row
    const int  dpj  = lane / 14;            // 0/1
    const bool aact = (lane < 28);

    // ---- time loop ----
    for (int t = 0; t < TSTEPS; t++) {
        // A: mem1 += c1, fire, pool -> p1h (duplicated k-layout, fp16 exact)
        if (aact) {
            #pragma unroll
            for (int i = 0; i < 3; i++) {
                int task = warp * 3 + i;                // 0..20
                int c    = task / 7;
                int pp   = task - 7 * c;
                int pj   = 2 * pp + dpj;
                int base = c * 840 + (2 * pj) * C1CP + 2 * pi;
                float2 ca = *reinterpret_cast<const float2*>(&c1s[base]);
                float2 cb = *reinterpret_cast<const float2*>(&c1s[base + C1CP]);
                float m0 = mr[i * 4 + 0] + ca.x;
                float m1 = mr[i * 4 + 1] + ca.y;
                float m2 = mr[i * 4 + 2] + cb.x;
                float m3 = mr[i * 4 + 3] + cb.y;
                float s0 = (m0 >= TH) ? TH : 0.f;
                float s1 = (m1 >= TH) ? TH : 0.f;
                float s2 = (m2 >= TH) ? TH : 0.f;
                float s3 = (m3 >= TH) ? TH : 0.f;
                mr[i * 4 + 0] = m0 - s0;
                mr[i * 4 + 1] = m1 - s1;
                mr[i * 4 + 2] = m2 - s2;
                mr[i * 4 + 3] = m3 - s3;
                __half val = __float2half_rn(0.25f * (s0 + s1 + s2 + s3));
                int cpad = pj + 2;                      // 2..15
                int rb   = c * 432 + (pi + 2) * 2 * P1P;
                if (cpad <= 10) p1h[rb + cpad] = val;             // h=0 row
                if (cpad >= 7)  p1h[rb + P1P + (cpad - 7)] = val; // h=1 row
            }
        }
        __syncthreads();

        // B: conv2 for oc pair. warps 0..2; lane = row*2+h; 7 cols x 2 oc per thread
        if (bact) {
            const int oc0 = 2 * warp, oc1 = oc0 + 1;
            float acc0[7], acc1[7];
            #pragma unroll
            for (int j = 0; j < 7; j++) { acc0[j] = b2a; acc1[j] = b2b; }
            #pragma unroll
            for (int ic = 0; ic < 3; ic++) {
                #pragma unroll
                for (int di = 0; di < 5; di++) {
                    // v window: 11 halves -> 12 floats (3x LDS.64, conflict-free)
                    const __half2* src = reinterpret_cast<const __half2*>(
                        &p1h[ic * 432 + (lane + 2 * di) * P1P]);
                    uint2 ra = *reinterpret_cast<const uint2*>(src);
                    uint2 rb2 = *reinterpret_cast<const uint2*>(src + 2);
                    uint2 rc = *reinterpret_cast<const uint2*>(src + 4);
                    float2 f0 = __half22float2(*reinterpret_cast<__half2*>(&ra.x));
                    float2 f1 = __half22float2(*reinterpret_cast<__half2*>(&ra.y));
                    float2 f2 = __half22float2(*reinterpret_cast<__half2*>(&rb2.x));
                    float2 f3 = __half22float2(*reinterpret_cast<__half2*>(&rb2.y));
                    float2 f4 = __half22float2(*reinterpret_cast<__half2*>(&rc.x));
                    float2 f5 = __half22float2(*reinterpret_cast<__half2*>(&rc.y));
                    float v[12] = {f0.x, f0.y, f1.x, f1.y, f2.x, f2.y,
                                   f3.x, f3.y, f4.x, f4.y, f5.x, f5.y};
                    // weight rows (broadcast): [oc][ic][di][8]
                    const float* wp0 = &w2d[((oc0 * 3 + ic) * 5 + di) * 8];
                    const float* wp1 = &w2d[((oc1 * 3 + ic) * 5 + di) * 8];
                    float4 wa4 = *reinterpret_cast<const float4*>(wp0);
                    float  wa5 = wp0[4];
                    float4 wb4 = *reinterpret_cast<const float4*>(wp1);
                    float  wb5 = wp1[4];
                    float w0[5] = {wa4.x, wa4.y, wa4.z, wa4.w, wa5};
                    float w1r[5] = {wb4.x, wb4.y, wb4.z, wb4.w, wb5};
                    #pragma unroll
                    for (int j = 0; j < 7; j++)
                        #pragma unroll
                        for (int dj = 0; dj < 5; dj++) {
                            acc0[j] += v[j + dj] * w0[dj];
                            acc1[j] += v[j + dj] * w1r[dj];
                        }
                }
            }
            float* dst0 = &s2L[oc0 * 196 + lane];
            float* dst1 = &s2L[oc1 * 196 + lane];
            #pragma unroll
            for (int j = 0; j < 7; j++) {
                float m  = m2a[j] + acc0[j];
                float sp = (m >= TH) ? TH : 0.f;
                m2a[j]   = m - sp;
                dst0[j * 28] = sp;
                float n  = m2b[j] + acc1[j];
                float sq = (n >= TH) ? TH : 0.f;
                m2b[j]   = n - sq;
                dst1[j * 28] = sq;
            }
        }
        __syncthreads();

        // C: 2x2 avg-pool layer 2 -> p2 (flatten order oc*49 + po*7 + qo)
        for (int idx = tid; idx < 294; idx += NT) {
            int oc = idx / 49, rem = idx - 49 * oc, po = rem / 7, qo = rem - 7 * po;
            float s = 0.f;
            #pragma unroll
            for (int a = 0; a < 2; a++)
                #pragma unroll
                for (int bb = 0; bb < 2; bb++) {
                    int r  = 2 * po + a, cc = 2 * qo + bb;
                    int h  = (cc >= 7) ? 1 : 0;
                    int jj = cc - 7 * h;
                    s += s2L[oc * 196 + jj * 28 + r * 2 + h];
                }
            p2s[idx] = 0.25f * s;
        }
        __syncthreads();

        // D: fc — warp w reduces row w (and 7+w for w<3)
        {
            float part = 0.f;
            const float* wrow = wf + warp * 294;
            for (int k = lane; k < 294; k += 32) part += p2s[k] * __ldg(&wrow[k]);
            #pragma unroll
            for (int s = 16; s > 0; s >>= 1) part += __shfl_xor_sync(0xffffffffu, part, s);
            if (lane == 0) fcsum[warp] = part;
            if (warp < 3) {
                float part2 = 0.f;
                const float* wrow2 = wf + (7 + warp) * 294;
                for (int k = lane; k < 294; k += 32) part2 += p2s[k] * __ldg(&wrow2[k]);
                #pragma unroll
                for (int s = 16; s > 0; s >>= 1) part2 += __shfl_xor_sync(0xffffffffu, part2, s);
                if (lane == 0) fcsum[7 + warp] = part2;
            }
        }
        __syncthreads();

        // E: mem3 update, fire, accumulate, emit running average at t=3,7
        if (tid < 10) {
            float m  = mem3s[tid] + fcsum[tid] + __ldg(&bf[tid]);
            float sp = (m >= TH) ? TH : 0.f;
            mem3s[tid] = m - sp;
            float a = acc3s[tid] + sp;
            acc3s[tid] = a;
            if (t == 3) out[(size_t)b * 10 + tid] = a * 0.25f;
            if (t == 7) out[(size_t)nb * 10 + (size_t)b * 10 + tid] = a * 0.125f;
        }
        __syncthreads();
    }
}

extern "C" void kernel_launch(void* const* d_in, const int* in_sizes, int n_in,
                              void* d_out, int out_size)
{
    const float* x  = (const float*)d_in[0];
    const float* w1 = (const float*)d_in[1];
    const float* b1 = (const float*)d_in[2];
    const float* w2 = (const float*)d_in[3];
    const float* b2 = (const float*)d_in[4];
    const float* wf = (const float*)d_in[5];
    const float* bf = (const float*)d_in[6];
    float* out = (float*)d_out;

    int nb = in_sizes[0] / 784;   // 4096
    snn_kernel<<<nb, NT>>>(x, w1, b1, w2, b2, wf, bf, out, nb);
}

// round 6
// speedup vs baseline: 1.0964x; 1.0964x over previous
#include <cuda_runtime.h>
#include <cuda_fp16.h>

// SpikeCNN fused: one block = one image, all 8 timesteps.
// R6: phase B = 6 warps x 1 oc (short critical path) + fp16 p1 (low LDS bytes)
//     + occupancy 4 blocks/SM (launch_bounds cap 72 regs).

#define TH 1.0f
#define TSTEPS 8
#define NT 224
#define XPITCH 33          // xpadT: col*33 + row (col-major)
#define C1CP 30            // c1s: c*840 + col*30 + row (col-major)
#define P1P 12             // p1h: [ic][rh(36)][k(12)] halves (k 0..10 used)

__global__ __launch_bounds__(NT, 4)
void snn_kernel(const float* __restrict__ x,
                const float* __restrict__ w1, const float* __restrict__ b1,
                const float* __restrict__ w2, const float* __restrict__ b2,
                const float* __restrict__ wf, const float* __restrict__ bf,
                float* __restrict__ out, int nb)
{
    __shared__ __align__(16) float  xpadT[32 * XPITCH];   // 1056 f32
    __shared__ __align__(16) float  c1s[3 * 28 * C1CP];   // 2520 f32 (col-major)
    __shared__ __align__(16) __half p1h[3 * 36 * P1P];    // 1296 halves
    __shared__ __align__(16) float  w2d[6 * 3 * 5 * 8];   // [oc][ic][di][8] padded rows
    __shared__ float s2L[6 * 196];          // oc*196 + j*28 + (row*2+h)
    __shared__ float p2s[294];
    __shared__ float fcsum[10], mem3s[10], acc3s[10];

    const int tid  = threadIdx.x;
    const int warp = tid >> 5;              // 0..6
    const int lane = tid & 31;
    const int b    = blockIdx.x;

    // ---- init ----
    for (int i = tid; i < 32 * XPITCH; i += NT)  xpadT[i] = 0.f;
    for (int i = tid; i < 3 * 36 * P1P; i += NT) p1h[i]   = __float2half(0.f);
    for (int i = tid; i < 720; i += NT)          w2d[i]   = 0.f;
    if (tid < 10) { mem3s[tid] = 0.f; acc3s[tid] = 0.f; }
    __syncthreads();
    for (int i = tid; i < 450; i += NT) {
        int g = i / 5, dj = i - 5 * g;      // g = oc*15 + ic*5 + di
        w2d[g * 8 + dj] = w2[i];
    }
    const float* xb = x + (size_t)b * 784;
    for (int i = tid; i < 784; i += NT) {
        int r = i / 28, c = i % 28;
        xpadT[(c + 2) * XPITCH + (r + 2)] = xb[i];
    }
    __syncthreads();

    // ---- conv1 (once): warps 0..5 -> (c = warp%3, colhalf = warp/3), lane = row ----
    if (warp < 6 && lane < 28) {
        int c = warp % 3, colbase = (warp / 3) * 14, row = lane;
        float wr[25];
        #pragma unroll
        for (int k = 0; k < 25; k++) wr[k] = __ldg(&w1[c * 25 + k]);
        float bias = __ldg(&b1[c]);
        float acc[14];
        #pragma unroll
        for (int j = 0; j < 14; j++) acc[j] = bias;
        #pragma unroll
        for (int di = 0; di < 5; di++) {
            float v[18];
            #pragma unroll
            for (int k = 0; k < 18; k++)
                v[k] = xpadT[(colbase + k) * XPITCH + row + di];
            #pragma unroll
            for (int j = 0; j < 14; j++)
                #pragma unroll
                for (int dj = 0; dj < 5; dj++)
                    acc[j] += v[j + dj] * wr[di * 5 + dj];
        }
        #pragma unroll
        for (int j = 0; j < 14; j++)
            c1s[c * 840 + (colbase + j) * C1CP + row] = acc[j];
    }
    __syncthreads();

    // ---- persistent register state ----
    float mr[12];                           // mem1: 3 tasks x 4 cells (all 7 warps)
    #pragma unroll
    for (int i = 0; i < 12; i++) mr[i] = 0.f;
    float m2r[7];                           // mem2: warps 0..5, oc = warp
    #pragma unroll
    for (int j = 0; j < 7; j++) m2r[j] = 0.f;
    const bool bact = (warp < 6 && lane < 28);
    const float b2r = bact ? __ldg(&b2[warp]) : 0.f;

    const int  pi   = lane % 14;            // phase-A pooled row
    const int  dpj  = lane / 14;            // 0/1
    const bool aact = (lane < 28);

    // ---- time loop ----
    for (int t = 0; t < TSTEPS; t++) {
        // A: mem1 += c1, fire, pool -> p1h (duplicated k-layout, fp16 exact)
        if (aact) {
            #pragma unroll
            for (int i = 0; i < 3; i++) {
                int task = warp * 3 + i;                // 0..20
                int c    = task / 7;
                int pp   = task - 7 * c;
                int pj   = 2 * pp + dpj;
                int base = c * 840 + (2 * pj) * C1CP + 2 * pi;
                float2 ca = *reinterpret_cast<const float2*>(&c1s[base]);
                float2 cb = *reinterpret_cast<const float2*>(&c1s[base + C1CP]);
                float m0 = mr[i * 4 + 0] + ca.x;
                float m1 = mr[i * 4 + 1] + ca.y;
                float m2 = mr[i * 4 + 2] + cb.x;
                float m3 = mr[i * 4 + 3] + cb.y;
                float s0 = (m0 >= TH) ? TH : 0.f;
                float s1 = (m1 >= TH) ? TH : 0.f;
                float s2 = (m2 >= TH) ? TH : 0.f;
                float s3 = (m3 >= TH) ? TH : 0.f;
                mr[i * 4 + 0] = m0 - s0;
                mr[i * 4 + 1] = m1 - s1;
                mr[i * 4 + 2] = m2 - s2;
                mr[i * 4 + 3] = m3 - s3;
                __half val = __float2half_rn(0.25f * (s0 + s1 + s2 + s3));
                int cpad = pj + 2;                      // 2..15
                int rb   = c * 432 + (pi + 2) * 2 * P1P;
                if (cpad <= 10) p1h[rb + cpad] = val;             // h=0 row
                if (cpad >= 7)  p1h[rb + P1P + (cpad - 7)] = val; // h=1 row
            }
        }
        __syncthreads();

        // B: conv2 + mem2 fire. warp = oc (0..5); lane = row*2+h; 7 cols/thread
        if (bact) {
            const int oc = warp;
            float acc[7];
            #pragma unroll
            for (int j = 0; j < 7; j++) acc[j] = b2r;
            #pragma unroll
            for (int ic = 0; ic < 3; ic++) {
                #pragma unroll
                for (int di = 0; di < 5; di++) {
                    // v window: 11 halves -> 12 floats (3x LDS.64, conflict-free)
                    const __half2* src = reinterpret_cast<const __half2*>(
                        &p1h[ic * 432 + (lane + 2 * di) * P1P]);
                    uint2 ra  = *reinterpret_cast<const uint2*>(src);
                    uint2 rb2 = *reinterpret_cast<const uint2*>(src + 2);
                    uint2 rc  = *reinterpret_cast<const uint2*>(src + 4);
                    float2 f0 = __half22float2(*reinterpret_cast<__half2*>(&ra.x));
                    float2 f1 = __half22float2(*reinterpret_cast<__half2*>(&ra.y));
                    float2 f2 = __half22float2(*reinterpret_cast<__half2*>(&rb2.x));
                    float2 f3 = __half22float2(*reinterpret_cast<__half2*>(&rb2.y));
                    float2 f4 = __half22float2(*reinterpret_cast<__half2*>(&rc.x));
                    float2 f5 = __half22float2(*reinterpret_cast<__half2*>(&rc.y));
                    float v[12] = {f0.x, f0.y, f1.x, f1.y, f2.x, f2.y,
                                   f3.x, f3.y, f4.x, f4.y, f5.x, f5.y};
                    // weight row (broadcast): [oc][ic][di][8]
                    const float* wp = &w2d[((oc * 3 + ic) * 5 + di) * 8];
                    float4 w4 = *reinterpret_cast<const float4*>(wp);
                    float  w5 = wp[4];
                    float wrow[5] = {w4.x, w4.y, w4.z, w4.w, w5};
                    #pragma unroll
                    for (int j = 0; j < 7; j++)
                        #pragma unroll
                        for (int dj = 0; dj < 5; dj++)
                            acc[j] += v[j + dj] * wrow[dj];
                }
            }
            float* dst = &s2L[oc * 196 + lane];
            #pragma unroll
            for (int j = 0; j < 7; j++) {
                float m  = m2r[j] + acc[j];
                float sp = (m >= TH) ? TH : 0.f;
                m2r[j]   = m - sp;
                dst[j * 28] = sp;
            }
        }
        __syncthreads();

        // C: 2x2 avg-pool layer 2 -> p2 (flatten order oc*49 + po*7 + qo)
        for (int idx = tid; idx < 294; idx += NT) {
            int oc = idx / 49, rem = idx - 49 * oc, po = rem / 7, qo = rem - 7 * po;
            float s = 0.f;
            #pragma unroll
            for (int a = 0; a < 2; a++)
                #pragma unroll
                for (int bb = 0; bb < 2; bb++) {
                    int r  = 2 * po + a, cc = 2 * qo + bb;
                    int h  = (cc >= 7) ? 1 : 0;
                    int jj = cc - 7 * h;
                    s += s2L[oc * 196 + jj * 28 + r * 2 + h];
                }
            p2s[idx] = 0.25f * s;
        }
        __syncthreads();

        // D: fc — warp w reduces row w (and 7+w for w<3)
        {
            float part = 0.f;
            const float* wrow = wf + warp * 294;
            for (int k = lane; k < 294; k += 32) part += p2s[k] * __ldg(&wrow[k]);
            #pragma unroll
            for (int s = 16; s > 0; s >>= 1) part += __shfl_xor_sync(0xffffffffu, part, s);
            if (lane == 0) fcsum[warp] = part;
            if (warp < 3) {
                float part2 = 0.f;
                const float* wrow2 = wf + (7 + warp) * 294;
                for (int k = lane; k < 294; k += 32) part2 += p2s[k] * __ldg(&wrow2[k]);
                #pragma unroll
                for (int s = 16; s > 0; s >>= 1) part2 += __shfl_xor_sync(0xffffffffu, part2, s);
                if (lane == 0) fcsum[7 + warp] = part2;
            }
        }
        __syncthreads();

        // E: mem3 update, fire, accumulate, emit running average at t=3,7
        if (tid < 10) {
            float m  = mem3s[tid] + fcsum[tid] + __ldg(&bf[tid]);
            float sp = (m >= TH) ? TH : 0.f;
            mem3s[tid] = m - sp;
            float a = acc3s[tid] + sp;
            acc3s[tid] = a;
            if (t == 3) out[(size_t)b * 10 + tid] = a * 0.25f;
            if (t == 7) out[(size_t)nb * 10 + (size_t)b * 10 + tid] = a * 0.125f;
        }
        __syncthreads();
    }
}

extern "C" void kernel_launch(void* const* d_in, const int* in_sizes, int n_in,
                              void* d_out, int out_size)
{
    const float* x  = (const float*)d_in[0];
    const float* w1 = (const float*)d_in[1];
    const float* b1 = (const float*)d_in[2];
    const float* w2 = (const float*)d_in[3];
    const float* b2 = (const float*)d_in[4];
    const float* wf = (const float*)d_in[5];
    const float* bf = (const float*)d_in[6];
    float* out = (float*)d_out;

    int nb = in_sizes[0] / 784;   // 4096
    snn_kernel<<<nb, NT>>>(x, w1, b1, w2, b2, wf, bf, out, nb);
}